// round 1
// baseline (speedup 1.0000x reference)
#include <cuda_runtime.h>
#include <cuda_bf16.h>
#include <cstdint>

// Problem constants
#define TWO_N   16384
#define NHALF   8192
#define DK      256
#define MT      128      // rows per CTA
#define NT      128      // cols per tile
#define SAPAD   264      // padded smem row stride in bf16 elements (528B: 16B-aligned, 4-bank shift/row)
#define SMEM_BYTES (3 * MT * SAPAD * 2)   // A tile + 2x B tile = 202752 bytes

// Scratch (device globals: no allocations allowed)
__device__ __align__(16) __nv_bfloat16 g_zn[TWO_N * DK];   // normalized, bf16
__device__ float g_rnorm[TWO_N];
__device__ float g_pos[NHALF];
__device__ float g_rowsum[TWO_N];

// ---------------- helpers ----------------
__device__ __forceinline__ float warp_sum(float v) {
    v += __shfl_xor_sync(0xffffffffu, v, 16);
    v += __shfl_xor_sync(0xffffffffu, v, 8);
    v += __shfl_xor_sync(0xffffffffu, v, 4);
    v += __shfl_xor_sync(0xffffffffu, v, 2);
    v += __shfl_xor_sync(0xffffffffu, v, 1);
    return v;
}

__device__ __forceinline__ float fast_ex2(float x) {
    float y;
    asm("ex2.approx.f32 %0, %1;" : "=f"(y) : "f"(x));
    return y;
}

__device__ __forceinline__ void cp16(void* dst_smem, const void* src_gmem) {
    unsigned s = (unsigned)__cvta_generic_to_shared(dst_smem);
    asm volatile("cp.async.cg.shared.global [%0], [%1], 16;\n" :: "r"(s), "l"(src_gmem));
}
__device__ __forceinline__ void cp_commit() { asm volatile("cp.async.commit_group;\n"); }
__device__ __forceinline__ void cp_wait0()  { asm volatile("cp.async.wait_group 0;\n"); }

__device__ __forceinline__ void mma16816(float* c, const uint32_t* a, uint32_t b0, uint32_t b1) {
    asm volatile(
        "mma.sync.aligned.m16n8k16.row.col.f32.bf16.bf16.f32 "
        "{%0,%1,%2,%3}, {%4,%5,%6,%7}, {%8,%9}, {%0,%1,%2,%3};\n"
        : "+f"(c[0]), "+f"(c[1]), "+f"(c[2]), "+f"(c[3])
        : "r"(a[0]), "r"(a[1]), "r"(a[2]), "r"(a[3]), "r"(b0), "r"(b1));
}

__device__ __forceinline__ unsigned pack_bf16(float a, float b) {
    __nv_bfloat162 h = __floats2bfloat162_rn(a, b);
    unsigned u;
    memcpy(&u, &h, 4);
    return u;
}

// ---------------- kernel 1: row-normalize, write bf16 ----------------
// grid 2048 x 256 threads: one warp per row
__global__ void normalize_kernel(const float* __restrict__ z1, const float* __restrict__ z2) {
    int warp = threadIdx.x >> 5, lane = threadIdx.x & 31;
    int row = blockIdx.x * 8 + warp;
    const float* src = (row < NHALF) ? (z1 + (size_t)row * DK)
                                     : (z2 + (size_t)(row - NHALF) * DK);
    float4 v0 = ((const float4*)src)[lane];
    float4 v1 = ((const float4*)src)[lane + 32];
    float ss = v0.x*v0.x + v0.y*v0.y + v0.z*v0.z + v0.w*v0.w
             + v1.x*v1.x + v1.y*v1.y + v1.z*v1.z + v1.w*v1.w;
    ss = warp_sum(ss);
    float rn = 1.0f / fmaxf(sqrtf(ss), 1e-6f);
    if (lane == 0) g_rnorm[row] = rn;

    uint2 w0, w1;
    w0.x = pack_bf16(v0.x * rn, v0.y * rn);
    w0.y = pack_bf16(v0.z * rn, v0.w * rn);
    w1.x = pack_bf16(v1.x * rn, v1.y * rn);
    w1.y = pack_bf16(v1.z * rn, v1.w * rn);
    uint2* dst = (uint2*)(g_zn + (size_t)row * DK);
    dst[lane]      = w0;
    dst[lane + 32] = w1;
}

// ---------------- kernel 2: positives in fp32 ----------------
// grid 1024 x 256: one warp per pair i
__global__ void pos_kernel(const float* __restrict__ z1, const float* __restrict__ z2) {
    int warp = threadIdx.x >> 5, lane = threadIdx.x & 31;
    int i = blockIdx.x * 8 + warp;
    const float* a = z1 + (size_t)i * DK;
    const float* b = z2 + (size_t)i * DK;
    float4 a0 = ((const float4*)a)[lane];
    float4 a1 = ((const float4*)a)[lane + 32];
    float4 b0 = ((const float4*)b)[lane];
    float4 b1 = ((const float4*)b)[lane + 32];
    float d = a0.x*b0.x + a0.y*b0.y + a0.z*b0.z + a0.w*b0.w
            + a1.x*b1.x + a1.y*b1.y + a1.z*b1.z + a1.w*b1.w;
    d = warp_sum(d);
    if (lane == 0) {
        float p = d * g_rnorm[i] * g_rnorm[i + NHALF];
        p = fminf(fmaxf(p, -1.0f + 1e-6f), 1.0f - 1e-6f);
        g_pos[i] = p;
    }
}

// ---------------- kernel 3: fused sim-GEMM + exp row-sum ----------------
// grid 128 CTAs x 256 threads. CTA b owns rows [b*128, b*128+128), sweeps all 128 col tiles.
__global__ __launch_bounds__(256, 1) void simloss_gemm() {
    extern __shared__ char smem_raw[];
    __nv_bfloat16* sAm = (__nv_bfloat16*)smem_raw;         // 128 x SAPAD
    __nv_bfloat16* sB0 = sAm + MT * SAPAD;                 // 2 buffers of 128 x SAPAD

    const int tid  = threadIdx.x;
    const int lane = tid & 31;
    const int warp = tid >> 5;
    const int wm = warp >> 1;      // 0..3  (M quadrant, 32 rows)
    const int wn = warp & 1;       // 0..1  (N half, 64 cols)
    const int g  = lane >> 2;      // 0..7
    const int tg = lane & 3;       // 0..3
    const int row0 = blockIdx.x * MT;

    // Prologue: A tile (resident) + B tile 0
    {
        const __nv_bfloat16* gA = g_zn + (size_t)row0 * DK;
        const __nv_bfloat16* gB = g_zn;   // tile 0 = rows [0,128)
        #pragma unroll
        for (int k = 0; k < 16; ++k) {
            int idx = tid + k * 256;
            int r = idx >> 5, c = (idx & 31) << 3;     // c in bf16 elems, 16B chunks
            cp16(sAm + r * SAPAD + c, gA + r * DK + c);
        }
        #pragma unroll
        for (int k = 0; k < 16; ++k) {
            int idx = tid + k * 256;
            int r = idx >> 5, c = (idx & 31) << 3;
            cp16(sB0 + r * SAPAD + c, gB + r * DK + c);
        }
        cp_commit();
        cp_wait0();
    }
    __syncthreads();

    float acc[2][8][4];
    #pragma unroll
    for (int mf = 0; mf < 2; ++mf)
        #pragma unroll
        for (int nf = 0; nf < 8; ++nf)
            #pragma unroll
            for (int q = 0; q < 4; ++q) acc[mf][nf][q] = 0.f;

    float racc[4] = {0.f, 0.f, 0.f, 0.f};   // per-thread row partial sums of exp
    const float SCALE = 14.426950408889634f; // (1/T) * log2(e) = 10*log2(e)

    const __nv_bfloat16* pa = sAm + (wm * 32 + g) * SAPAD + tg * 2;

    for (int t = 0; t < 128; ++t) {
        __nv_bfloat16* sBc = sB0 + (t & 1) * (MT * SAPAD);
        // Prefetch next B tile into the other buffer
        if (t + 1 < 128) {
            __nv_bfloat16* sBn = sB0 + ((t + 1) & 1) * (MT * SAPAD);
            const __nv_bfloat16* gB = g_zn + (size_t)(t + 1) * NT * DK;
            #pragma unroll
            for (int k = 0; k < 16; ++k) {
                int idx = tid + k * 256;
                int r = idx >> 5, c = (idx & 31) << 3;
                cp16(sBn + r * SAPAD + c, gB + r * DK + c);
            }
        }
        cp_commit();

        const __nv_bfloat16* pb = sBc + (wn * 64 + g) * SAPAD + tg * 2;

        #pragma unroll
        for (int ks = 0; ks < 16; ++ks) {
            const int k0 = ks * 16;
            uint32_t a[2][4];
            #pragma unroll
            for (int mf = 0; mf < 2; ++mf) {
                const __nv_bfloat16* base = pa + mf * 16 * SAPAD + k0;
                a[mf][0] = *(const uint32_t*)(base);
                a[mf][1] = *(const uint32_t*)(base + 8 * SAPAD);
                a[mf][2] = *(const uint32_t*)(base + 8);
                a[mf][3] = *(const uint32_t*)(base + 8 * SAPAD + 8);
            }
            #pragma unroll
            for (int nf = 0; nf < 8; ++nf) {
                const __nv_bfloat16* bb = pb + nf * 8 * SAPAD + k0;
                uint32_t b0 = *(const uint32_t*)(bb);
                uint32_t b1 = *(const uint32_t*)(bb + 8);
                mma16816(acc[0][nf], a[0], b0, b1);
                mma16816(acc[1][nf], a[1], b0, b1);
            }
        }

        // Epilogue: exp + row accumulate (diag mask only in the diagonal tile)
        const int colT = t * NT + wn * 64 + tg * 2;
        const bool isDiag = (t == (int)blockIdx.x);
        #pragma unroll
        for (int mf = 0; mf < 2; ++mf) {
            const int r0g = row0 + wm * 32 + mf * 16 + g;
            #pragma unroll
            for (int nf = 0; nf < 8; ++nf) {
                const int c0g = colT + nf * 8;
                float e0 = fast_ex2(acc[mf][nf][0] * SCALE);
                float e1 = fast_ex2(acc[mf][nf][1] * SCALE);
                float e2 = fast_ex2(acc[mf][nf][2] * SCALE);
                float e3 = fast_ex2(acc[mf][nf][3] * SCALE);
                if (isDiag) {
                    if (r0g     == c0g)     e0 = 0.f;
                    if (r0g     == c0g + 1) e1 = 0.f;
                    if (r0g + 8 == c0g)     e2 = 0.f;
                    if (r0g + 8 == c0g + 1) e3 = 0.f;
                }
                racc[mf * 2]     += e0 + e1;
                racc[mf * 2 + 1] += e2 + e3;
                acc[mf][nf][0] = 0.f; acc[mf][nf][1] = 0.f;
                acc[mf][nf][2] = 0.f; acc[mf][nf][3] = 0.f;
            }
        }

        cp_wait0();
        __syncthreads();
    }

    // Reduce over tg lanes (4 lanes share the same rows)
    #pragma unroll
    for (int k2 = 0; k2 < 4; ++k2) {
        racc[k2] += __shfl_xor_sync(0xffffffffu, racc[k2], 1);
        racc[k2] += __shfl_xor_sync(0xffffffffu, racc[k2], 2);
    }

    // Merge the two wn warps per row deterministically via smem (no atomics)
    float* sred = (float*)smem_raw;   // reuse tile smem: 128 floats
    __syncthreads();
    if (wn == 0 && tg == 0) {
        #pragma unroll
        for (int k2 = 0; k2 < 4; ++k2) {
            int rl = wm * 32 + (k2 >> 1) * 16 + (k2 & 1) * 8 + g;
            sred[rl] = racc[k2];
        }
    }
    __syncthreads();
    if (wn == 1 && tg == 0) {
        #pragma unroll
        for (int k2 = 0; k2 < 4; ++k2) {
            int rl = wm * 32 + (k2 >> 1) * 16 + (k2 & 1) * 8 + g;
            g_rowsum[row0 + rl] = sred[rl] + racc[k2];
        }
    }
}

// ---------------- kernel 4: final reduce ----------------
__global__ void final_kernel(float* __restrict__ out) {
    __shared__ float s1[256], s2[256];
    int tid = threadIdx.x;
    float a = 0.f, p = 0.f;
    for (int i = tid; i < TWO_N; i += 256) a += logf(g_rowsum[i]);
    for (int i = tid; i < NHALF; i += 256) p += g_pos[i];
    s1[tid] = a; s2[tid] = p;
    __syncthreads();
    for (int s = 128; s > 0; s >>= 1) {
        if (tid < s) { s1[tid] += s1[tid + s]; s2[tid] += s2[tid + s]; }
        __syncthreads();
    }
    if (tid == 0) out[0] = (s1[0] - 2.0f * s2[0] * 10.0f) / (float)TWO_N;
}

// ---------------- launch ----------------
extern "C" void kernel_launch(void* const* d_in, const int* in_sizes, int n_in,
                              void* d_out, int out_size) {
    const float* z1 = (const float*)d_in[0];
    const float* z2 = (const float*)d_in[1];
    float* out = (float*)d_out;

    normalize_kernel<<<2048, 256>>>(z1, z2);
    pos_kernel<<<1024, 256>>>(z1, z2);
    cudaFuncSetAttribute(simloss_gemm, cudaFuncAttributeMaxDynamicSharedMemorySize, SMEM_BYTES);
    simloss_gemm<<<128, 256, SMEM_BYTES>>>();
    final_kernel<<<1, 256>>>(out);
}

// round 3
// speedup vs baseline: 1.0144x; 1.0144x over previous
#include <cuda_runtime.h>
#include <cuda_bf16.h>
#include <cstdint>

// ---------------- problem constants ----------------
#define TWO_N   16384
#define NHALF   8192
#define DK      256
#define MT      128
#define NT      128
#define NTILES  128
#define SAPAD   264      // padded smem row stride in bf16 (528B; conflict-free for ldmatrix)
#define A_ELEMS (MT * SAPAD)
#define B_BYTES (MT * SAPAD * 2)
#define SMEM_BYTES (3 * MT * SAPAD * 2)   // A + 2x B = 202752 B

// ---------------- device scratch ----------------
__device__ __align__(16) __nv_bfloat16 g_zn[TWO_N * DK];
__device__ float g_rnorm[TWO_N];
__device__ float g_pos[NHALF];
__device__ float g_rowsum[TWO_N];
__device__ float g_partA[64];
__device__ float g_partB[64];

// ---------------- helpers ----------------
__device__ __forceinline__ float fast_ex2(float x) {
    float y;
    asm("ex2.approx.f32 %0, %1;" : "=f"(y) : "f"(x));
    return y;
}
__device__ __forceinline__ uint32_t smem_u32(const void* p) {
    uint32_t a;
    asm("{ .reg .u64 t; cvta.to.shared.u64 t, %1; cvt.u32.u64 %0, t; }" : "=r"(a) : "l"(p));
    return a;
}
__device__ __forceinline__ void cp16(uint32_t dst, const void* src) {
    asm volatile("cp.async.cg.shared.global [%0], [%1], 16;\n" :: "r"(dst), "l"(src));
}
__device__ __forceinline__ void cp_commit() { asm volatile("cp.async.commit_group;\n"); }
__device__ __forceinline__ void cp_wait0()  { asm volatile("cp.async.wait_group 0;\n"); }

__device__ __forceinline__ void ldsm4(uint32_t* r, uint32_t addr) {
    asm volatile("ldmatrix.sync.aligned.m8n8.x4.shared.b16 {%0,%1,%2,%3}, [%4];"
                 : "=r"(r[0]), "=r"(r[1]), "=r"(r[2]), "=r"(r[3]) : "r"(addr));
}
__device__ __forceinline__ void mma16816(float* c, const uint32_t* a, uint32_t b0, uint32_t b1) {
    asm volatile(
        "mma.sync.aligned.m16n8k16.row.col.f32.bf16.bf16.f32 "
        "{%0,%1,%2,%3}, {%4,%5,%6,%7}, {%8,%9}, {%0,%1,%2,%3};\n"
        : "+f"(c[0]), "+f"(c[1]), "+f"(c[2]), "+f"(c[3])
        : "r"(a[0]), "r"(a[1]), "r"(a[2]), "r"(a[3]), "r"(b0), "r"(b1));
}

// ---------------- kernel 1: row-normalize -> bf16 ----------------
__global__ void normalize_kernel(const float* __restrict__ z1, const float* __restrict__ z2) {
    int warp = threadIdx.x >> 5, lane = threadIdx.x & 31;
    int row = blockIdx.x * 8 + warp;
    const float* src = (row < NHALF) ? (z1 + (size_t)row * DK)
                                     : (z2 + (size_t)(row - NHALF) * DK);
    float4 v0 = ((const float4*)src)[lane];
    float4 v1 = ((const float4*)src)[lane + 32];
    float ss = v0.x*v0.x + v0.y*v0.y + v0.z*v0.z + v0.w*v0.w
             + v1.x*v1.x + v1.y*v1.y + v1.z*v1.z + v1.w*v1.w;
    #pragma unroll
    for (int o = 16; o > 0; o >>= 1) ss += __shfl_xor_sync(0xffffffffu, ss, o);
    float rn = 1.0f / fmaxf(sqrtf(ss), 1e-6f);
    if (lane == 0) g_rnorm[row] = rn;

    __nv_bfloat162 w0a = __floats2bfloat162_rn(v0.x * rn, v0.y * rn);
    __nv_bfloat162 w0b = __floats2bfloat162_rn(v0.z * rn, v0.w * rn);
    __nv_bfloat162 w1a = __floats2bfloat162_rn(v1.x * rn, v1.y * rn);
    __nv_bfloat162 w1b = __floats2bfloat162_rn(v1.z * rn, v1.w * rn);
    uint2 p0, p1;
    memcpy(&p0.x, &w0a, 4); memcpy(&p0.y, &w0b, 4);
    memcpy(&p1.x, &w1a, 4); memcpy(&p1.y, &w1b, 4);
    uint2* dst = (uint2*)(g_zn + (size_t)row * DK);
    dst[lane]      = p0;
    dst[lane + 32] = p1;
}

// ---------------- kernel 2: fp32 positives ----------------
__global__ void pos_kernel(const float* __restrict__ z1, const float* __restrict__ z2) {
    int warp = threadIdx.x >> 5, lane = threadIdx.x & 31;
    int i = blockIdx.x * 8 + warp;
    const float* a = z1 + (size_t)i * DK;
    const float* b = z2 + (size_t)i * DK;
    float4 a0 = ((const float4*)a)[lane];
    float4 a1 = ((const float4*)a)[lane + 32];
    float4 b0 = ((const float4*)b)[lane];
    float4 b1 = ((const float4*)b)[lane + 32];
    float d = a0.x*b0.x + a0.y*b0.y + a0.z*b0.z + a0.w*b0.w
            + a1.x*b1.x + a1.y*b1.y + a1.z*b1.z + a1.w*b1.w;
    #pragma unroll
    for (int o = 16; o > 0; o >>= 1) d += __shfl_xor_sync(0xffffffffu, d, o);
    if (lane == 0) {
        float p = d * g_rnorm[i] * g_rnorm[i + NHALF];
        p = fminf(fmaxf(p, -1.0f + 1e-6f), 1.0f - 1e-6f);
        g_pos[i] = p;
    }
}

// ---------------- kernel 3: HMMA fused sim-GEMM + pipelined exp epilogue ----------------
// 512 threads: warp w -> wm = w>>2 (rows wm*32..+32), wn = w&3 (cols wn*32..+32)
__global__ __launch_bounds__(512, 1) void simloss_hmma() {
    extern __shared__ char smem_raw[];
    const uint32_t sbase = smem_u32(smem_raw);
    const uint32_t sA  = sbase;
    const uint32_t sB0 = sbase + (uint32_t)(MT * SAPAD * 2);

    const int tid  = threadIdx.x;
    const int lane = tid & 31;
    const int w    = tid >> 5;
    const int wm   = w >> 2;
    const int wn   = w & 3;
    const int g    = lane >> 2;
    const int tg   = lane & 3;
    const int row0 = blockIdx.x * MT;

    // ---- prologue loads: A (resident) + B tile 0 ----
    {
        const __nv_bfloat16* gA = g_zn + (size_t)row0 * DK;
        #pragma unroll
        for (int k = 0; k < 8; ++k) {
            int id = tid + k * 512;
            int r = id >> 5, cc = id & 31;
            cp16(sA + (uint32_t)((r * SAPAD + cc * 8) * 2), gA + (size_t)r * DK + cc * 8);
        }
        #pragma unroll
        for (int k = 0; k < 8; ++k) {
            int id = tid + k * 512;
            int r = id >> 5, cc = id & 31;
            cp16(sB0 + (uint32_t)((r * SAPAD + cc * 8) * 2), g_zn + (size_t)r * DK + cc * 8);
        }
        cp_commit(); cp_wait0();
    }
    __syncthreads();

    // ldmatrix per-lane base addresses (byte offsets into smem)
    const int lrow = lane & 15;
    const int lchk = lane >> 4;           // 0/1 -> k-chunk of 8 elems
    uint32_t aAddr0 = sA + (uint32_t)(((wm * 32 +  0 + lrow) * SAPAD + lchk * 8) * 2);
    uint32_t aAddr1 = sA + (uint32_t)(((wm * 32 + 16 + lrow) * SAPAD + lchk * 8) * 2);
    uint32_t bOff0  =       (uint32_t)(((wn * 32 +  0 + lrow) * SAPAD + lchk * 8) * 2);
    uint32_t bOff1  =       (uint32_t)(((wn * 32 + 16 + lrow) * SAPAD + lchk * 8) * 2);

    float acc[2][4][4];
    #pragma unroll
    for (int mf = 0; mf < 2; ++mf)
        #pragma unroll
        for (int nf = 0; nf < 4; ++nf)
            #pragma unroll
            for (int q = 0; q < 4; ++q) acc[mf][nf][q] = 0.f;

    float prv[32];
    float racc[4] = {0.f, 0.f, 0.f, 0.f};
    const float SCALE = 14.426950408889634f;   // 10 * log2(e)

    for (int t = 0; t < NTILES; ++t) {
        const uint32_t sBc = sB0 + (uint32_t)((t & 1) * B_BYTES);

        // prefetch B(t+1) into the other buffer
        if (t + 1 < NTILES) {
            const uint32_t sBn = sB0 + (uint32_t)(((t + 1) & 1) * B_BYTES);
            const __nv_bfloat16* gB = g_zn + (size_t)(t + 1) * NT * DK;
            #pragma unroll
            for (int k = 0; k < 8; ++k) {
                int id = tid + k * 512;
                int r = id >> 5, cc = id & 31;
                cp16(sBn + (uint32_t)((r * SAPAD + cc * 8) * 2), gB + (size_t)r * DK + cc * 8);
            }
        }
        cp_commit();

        const bool hasPrev = (t > 0);
        const bool pdiag   = hasPrev && ((t - 1) == (int)blockIdx.x);
        const int  pcol    = (t - 1) * NT + wn * 32 + tg * 2;

        #pragma unroll
        for (int ks = 0; ks < 16; ++ks) {
            const uint32_t kb = (uint32_t)(ks * 32);   // 16 bf16 = 32 bytes
            uint32_t a0[4], a1[4], bA[4], bB[4];
            ldsm4(a0, aAddr0 + kb);
            ldsm4(a1, aAddr1 + kb);
            ldsm4(bA, sBc + bOff0 + kb);
            ldsm4(bB, sBc + bOff1 + kb);

            mma16816(acc[0][0], a0, bA[0], bA[2]);
            mma16816(acc[1][0], a1, bA[0], bA[2]);
            mma16816(acc[0][1], a0, bA[1], bA[3]);
            mma16816(acc[1][1], a1, bA[1], bA[3]);
            mma16816(acc[0][2], a0, bB[0], bB[2]);
            mma16816(acc[1][2], a1, bB[0], bB[2]);
            mma16816(acc[0][3], a0, bB[1], bB[3]);
            mma16816(acc[1][3], a1, bB[1], bB[3]);

            // pipelined epilogue: 2 elements of previous tile per ks step
            if (hasPrev) {
                #pragma unroll
                for (int u = 0; u < 2; ++u) {
                    const int idx = ks * 2 + u;
                    const int mf = idx >> 4, nf = (idx >> 2) & 3, q = idx & 3;
                    float e = fast_ex2(prv[idx] * SCALE);
                    if (pdiag) {
                        int r = row0 + wm * 32 + mf * 16 + (q >> 1) * 8 + g;
                        int c = pcol + nf * 8 + (q & 1);
                        if (r == c) e = 0.f;
                    }
                    racc[mf * 2 + (q >> 1)] += e;
                }
            }
        }

        // hand off acc -> prv, reset acc
        #pragma unroll
        for (int mf = 0; mf < 2; ++mf)
            #pragma unroll
            for (int nf = 0; nf < 4; ++nf)
                #pragma unroll
                for (int q = 0; q < 4; ++q) {
                    prv[mf * 16 + nf * 4 + q] = acc[mf][nf][q];
                    acc[mf][nf][q] = 0.f;
                }

        cp_wait0();
        __syncthreads();
    }

    // final epilogue: tile 127
    {
        const bool pdiag = ((NTILES - 1) == (int)blockIdx.x);
        const int  pcol  = (NTILES - 1) * NT + wn * 32 + tg * 2;
        #pragma unroll
        for (int idx = 0; idx < 32; ++idx) {
            const int mf = idx >> 4, nf = (idx >> 2) & 3, q = idx & 3;
            float e = fast_ex2(prv[idx] * SCALE);
            if (pdiag) {
                int r = row0 + wm * 32 + mf * 16 + (q >> 1) * 8 + g;
                int c = pcol + nf * 8 + (q & 1);
                if (r == c) e = 0.f;
            }
            racc[mf * 2 + (q >> 1)] += e;
        }
    }

    // reduce over the 4 lanes sharing each row
    #pragma unroll
    for (int k2 = 0; k2 < 4; ++k2) {
        racc[k2] += __shfl_xor_sync(0xffffffffu, racc[k2], 1);
        racc[k2] += __shfl_xor_sync(0xffffffffu, racc[k2], 2);
    }

    // merge 4 wn-warps per row via smem (deterministic, no atomics)
    float* sred = (float*)smem_raw;    // 4 * 128 floats
    __syncthreads();
    if (tg == 0) {
        #pragma unroll
        for (int mf = 0; mf < 2; ++mf)
            #pragma unroll
            for (int h = 0; h < 2; ++h) {
                int rl = wm * 32 + mf * 16 + h * 8 + g;
                sred[wn * 128 + rl] = racc[mf * 2 + h];
            }
    }
    __syncthreads();
    if (tid < 128) {
        g_rowsum[row0 + tid] = sred[tid] + sred[128 + tid] + sred[256 + tid] + sred[384 + tid];
    }
}

// ---------------- kernel 4: two-stage final reduce ----------------
__global__ void reduce1_kernel() {
    __shared__ float sa[256], sb[256];
    int b = blockIdx.x, tid = threadIdx.x;
    float a = logf(g_rowsum[b * 256 + tid]);
    float p = (tid < 128) ? g_pos[b * 128 + tid] : 0.f;
    sa[tid] = a; sb[tid] = p;
    __syncthreads();
    for (int s = 128; s > 0; s >>= 1) {
        if (tid < s) { sa[tid] += sa[tid + s]; sb[tid] += sb[tid + s]; }
        __syncthreads();
    }
    if (tid == 0) { g_partA[b] = sa[0]; g_partB[b] = sb[0]; }
}

__global__ void reduce2_kernel(float* __restrict__ out) {
    __shared__ float sa[64], sb[64];
    int tid = threadIdx.x;
    sa[tid] = g_partA[tid]; sb[tid] = g_partB[tid];
    __syncthreads();
    for (int s = 32; s > 0; s >>= 1) {
        if (tid < s) { sa[tid] += sa[tid + s]; sb[tid] += sb[tid + s]; }
        __syncthreads();
    }
    if (tid == 0) out[0] = (sa[0] - 20.0f * sb[0]) / (float)TWO_N;
}

// ---------------- launch ----------------
extern "C" void kernel_launch(void* const* d_in, const int* in_sizes, int n_in,
                              void* d_out, int out_size) {
    const float* z1 = (const float*)d_in[0];
    const float* z2 = (const float*)d_in[1];
    float* out = (float*)d_out;

    normalize_kernel<<<2048, 256>>>(z1, z2);
    pos_kernel<<<1024, 256>>>(z1, z2);
    cudaFuncSetAttribute(simloss_hmma, cudaFuncAttributeMaxDynamicSharedMemorySize, SMEM_BYTES);
    simloss_hmma<<<128, 512, SMEM_BYTES>>>();
    reduce1_kernel<<<64, 256>>>();
    reduce2_kernel<<<1, 64>>>(out);
}

// round 4
// speedup vs baseline: 1.7291x; 1.7045x over previous
#include <cuda_runtime.h>
#include <cuda_bf16.h>
#include <cstdint>

// ---------------- problem constants ----------------
#define TWO_N   16384
#define NHALF   8192
#define DK      256
#define MT      128
#define NT      128
#define SAPAD   264      // padded smem row stride in bf16 (528B; conflict-free ldmatrix)
#define TILE_BYTES2 (MT * SAPAD * 2)

// smem: scratch (2KB) | A tile | B tile x2
#define SM_SCRATCH 0
#define SM_A       2048
#define SM_B       (SM_A + TILE_BYTES2)
#define SMEM_BYTES (SM_B + 2 * TILE_BYTES2)   // 204800 B

// ---------------- device scratch ----------------
__device__ __align__(16) __nv_bfloat16 g_zn[TWO_N * DK];
__device__ float g_rnorm[TWO_N];
__device__ float g_pos[NHALF];
__device__ float g_rowsum[TWO_N];
__device__ float g_partA[64];
__device__ float g_partB[64];
// column-sum contributions: [band(writer) * 4 + wm][col]  (32 MB, single-writer)
__device__ float g_cs[128 * 4 * TWO_N];
// direct row partials: [half][band][row]  (zeroed each run)
__device__ float g_rsp[2 * 128 * 128];

// ---------------- helpers ----------------
__device__ __forceinline__ float fast_ex2(float x) {
    float y;
    asm("ex2.approx.f32 %0, %1;" : "=f"(y) : "f"(x));
    return y;
}
__device__ __forceinline__ uint32_t smem_u32(const void* p) {
    uint32_t a;
    asm("{ .reg .u64 t; cvta.to.shared.u64 t, %1; cvt.u32.u64 %0, t; }" : "=r"(a) : "l"(p));
    return a;
}
__device__ __forceinline__ void cp16(uint32_t dst, const void* src) {
    asm volatile("cp.async.cg.shared.global [%0], [%1], 16;\n" :: "r"(dst), "l"(src));
}
__device__ __forceinline__ void cp_commit() { asm volatile("cp.async.commit_group;\n"); }
__device__ __forceinline__ void cp_wait0()  { asm volatile("cp.async.wait_group 0;\n"); }

__device__ __forceinline__ void ldsm4(uint32_t* r, uint32_t addr) {
    asm volatile("ldmatrix.sync.aligned.m8n8.x4.shared.b16 {%0,%1,%2,%3}, [%4];"
                 : "=r"(r[0]), "=r"(r[1]), "=r"(r[2]), "=r"(r[3]) : "r"(addr));
}
__device__ __forceinline__ void mma16816(float* c, const uint32_t* a, uint32_t b0, uint32_t b1) {
    asm volatile(
        "mma.sync.aligned.m16n8k16.row.col.f32.bf16.bf16.f32 "
        "{%0,%1,%2,%3}, {%4,%5,%6,%7}, {%8,%9}, {%0,%1,%2,%3};\n"
        : "+f"(c[0]), "+f"(c[1]), "+f"(c[2]), "+f"(c[3])
        : "r"(a[0]), "r"(a[1]), "r"(a[2]), "r"(a[3]), "r"(b0), "r"(b1));
}

// ---------------- kernel 1: row-normalize -> bf16 ----------------
__global__ void normalize_kernel(const float* __restrict__ z1, const float* __restrict__ z2) {
    int warp = threadIdx.x >> 5, lane = threadIdx.x & 31;
    int row = blockIdx.x * 8 + warp;
    const float* src = (row < NHALF) ? (z1 + (size_t)row * DK)
                                     : (z2 + (size_t)(row - NHALF) * DK);
    float4 v0 = ((const float4*)src)[lane];
    float4 v1 = ((const float4*)src)[lane + 32];
    float ss = v0.x*v0.x + v0.y*v0.y + v0.z*v0.z + v0.w*v0.w
             + v1.x*v1.x + v1.y*v1.y + v1.z*v1.z + v1.w*v1.w;
    #pragma unroll
    for (int o = 16; o > 0; o >>= 1) ss += __shfl_xor_sync(0xffffffffu, ss, o);
    float rn = 1.0f / fmaxf(sqrtf(ss), 1e-6f);
    if (lane == 0) g_rnorm[row] = rn;

    __nv_bfloat162 w0a = __floats2bfloat162_rn(v0.x * rn, v0.y * rn);
    __nv_bfloat162 w0b = __floats2bfloat162_rn(v0.z * rn, v0.w * rn);
    __nv_bfloat162 w1a = __floats2bfloat162_rn(v1.x * rn, v1.y * rn);
    __nv_bfloat162 w1b = __floats2bfloat162_rn(v1.z * rn, v1.w * rn);
    uint2 p0, p1;
    memcpy(&p0.x, &w0a, 4); memcpy(&p0.y, &w0b, 4);
    memcpy(&p1.x, &w1a, 4); memcpy(&p1.y, &w1b, 4);
    uint2* dst = (uint2*)(g_zn + (size_t)row * DK);
    dst[lane]      = p0;
    dst[lane + 32] = p1;
}

// ---------------- kernel 2: fp32 positives ----------------
__global__ void pos_kernel(const float* __restrict__ z1, const float* __restrict__ z2) {
    int warp = threadIdx.x >> 5, lane = threadIdx.x & 31;
    int i = blockIdx.x * 8 + warp;
    const float* a = z1 + (size_t)i * DK;
    const float* b = z2 + (size_t)i * DK;
    float4 a0 = ((const float4*)a)[lane];
    float4 a1 = ((const float4*)a)[lane + 32];
    float4 b0 = ((const float4*)b)[lane];
    float4 b1 = ((const float4*)b)[lane + 32];
    float d = a0.x*b0.x + a0.y*b0.y + a0.z*b0.z + a0.w*b0.w
            + a1.x*b1.x + a1.y*b1.y + a1.z*b1.z + a1.w*b1.w;
    #pragma unroll
    for (int o = 16; o > 0; o >>= 1) d += __shfl_xor_sync(0xffffffffu, d, o);
    if (lane == 0) {
        float p = d * g_rnorm[i] * g_rnorm[i + NHALF];
        p = fminf(fmaxf(p, -1.0f + 1e-6f), 1.0f - 1e-6f);
        g_pos[i] = p;
    }
}

// ---------------- kernel 2b: zero row-partial buffer ----------------
__global__ void zero_rsp_kernel() {
    int i = blockIdx.x * 256 + threadIdx.x;
    ((float4*)g_rsp)[i] = make_float4(0.f, 0.f, 0.f, 0.f);   // 32 blocks * 256 * 4 = 32768
}

// ---------------- kernel 3: symmetric HMMA fused sim-GEMM ----------------
// 128 CTAs x 512 thr. Pair p = blk>>1 couples bands (p, 127-p); even CTA: band p
// tiles t=p..p+64; odd CTA: band p tiles t=p+65..127 then band 127-p tiles t=127-p..127.
__global__ __launch_bounds__(512, 1) void simloss_sym() {
    extern __shared__ char smem_raw[];
    const uint32_t sbase = smem_u32(smem_raw);
    const uint32_t sA  = sbase + SM_A;
    const uint32_t sB0 = sbase + SM_B;

    const int tid  = threadIdx.x;
    const int lane = tid & 31;
    const int w    = tid >> 5;
    const int wm   = w >> 2;
    const int wn   = w & 3;
    const int g    = lane >> 2;
    const int tg   = lane & 3;

    const int p    = blockIdx.x >> 1;
    const int half = blockIdx.x & 1;

    int segBand[2], segT0[2], segT1[2], nseg = 0;
    if (!half) {
        segBand[0] = p; segT0[0] = p; segT1[0] = p + 64; nseg = 1;
    } else {
        if (p + 65 <= 127) { segBand[nseg] = p; segT0[nseg] = p + 65; segT1[nseg] = 127; ++nseg; }
        segBand[nseg] = 127 - p; segT0[nseg] = 127 - p; segT1[nseg] = 127; ++nseg;
    }

    // ldmatrix per-lane offsets
    const int lrow = lane & 15;
    const int lchk = lane >> 4;
    const uint32_t aOff = (uint32_t)(((wm * 32 + lrow) * SAPAD + lchk * 8) * 2);
    const uint32_t aOff2 = aOff + (uint32_t)(16 * SAPAD * 2);
    const uint32_t bOff = (uint32_t)(((wn * 32 + lrow) * SAPAD + lchk * 8) * 2);
    const uint32_t bOff2 = bOff + (uint32_t)(16 * SAPAD * 2);

    const float SCALE = 14.426950408889634f;   // 10 * log2(e)
    float* sred = (float*)smem_raw;            // 512 floats scratch

    for (int s = 0; s < nseg; ++s) {
        const int band = segBand[s], t0 = segT0[s], t1 = segT1[s];
        const int nb = t1 - t0 + 1;

        // load A(band) + B(t0)
        {
            const __nv_bfloat16* gA = g_zn + (size_t)band * MT * DK;
            const __nv_bfloat16* gB = g_zn + (size_t)t0 * NT * DK;
            #pragma unroll
            for (int k = 0; k < 8; ++k) {
                int id = tid + k * 512;
                int r = id >> 5, cc = id & 31;
                uint32_t so = (uint32_t)((r * SAPAD + cc * 8) * 2);
                cp16(sA + so, gA + (size_t)r * DK + cc * 8);
                cp16(sB0 + so, gB + (size_t)r * DK + cc * 8);
            }
            cp_commit(); cp_wait0();
        }
        __syncthreads();

        float acc[2][4][4];
        #pragma unroll
        for (int mf = 0; mf < 2; ++mf)
            #pragma unroll
            for (int nf = 0; nf < 4; ++nf)
                #pragma unroll
                for (int q = 0; q < 4; ++q) acc[mf][nf][q] = 0.f;
        float racc[4] = {0.f, 0.f, 0.f, 0.f};

        for (int i = 0; i < nb; ++i) {
            const int t = t0 + i;
            const uint32_t sBc = sB0 + (uint32_t)((i & 1) * TILE_BYTES2);

            if (i + 1 < nb) {
                const uint32_t sBn = sB0 + (uint32_t)(((i + 1) & 1) * TILE_BYTES2);
                const __nv_bfloat16* gB = g_zn + (size_t)(t + 1) * NT * DK;
                #pragma unroll
                for (int k = 0; k < 8; ++k) {
                    int id = tid + k * 512;
                    int r = id >> 5, cc = id & 31;
                    cp16(sBn + (uint32_t)((r * SAPAD + cc * 8) * 2), gB + (size_t)r * DK + cc * 8);
                }
            }
            cp_commit();

            #pragma unroll
            for (int ks = 0; ks < 16; ++ks) {
                const uint32_t kb = (uint32_t)(ks * 32);
                uint32_t a0[4], a1[4], bA[4], bB[4];
                ldsm4(a0, sA + aOff + kb);
                ldsm4(a1, sA + aOff2 + kb);
                ldsm4(bA, sBc + bOff + kb);
                ldsm4(bB, sBc + bOff2 + kb);

                mma16816(acc[0][0], a0, bA[0], bA[2]);
                mma16816(acc[1][0], a1, bA[0], bA[2]);
                mma16816(acc[0][1], a0, bA[1], bA[3]);
                mma16816(acc[1][1], a1, bA[1], bA[3]);
                mma16816(acc[0][2], a0, bB[0], bB[2]);
                mma16816(acc[1][2], a1, bB[0], bB[2]);
                mma16816(acc[0][3], a0, bB[1], bB[3]);
                mma16816(acc[1][3], a1, bB[1], bB[3]);
            }

            // ---- epilogue: exp, row accumulate, column accumulate (symmetry) ----
            const bool offd = (t != band);
            float cc8[8];
            #pragma unroll
            for (int j = 0; j < 8; ++j) cc8[j] = 0.f;

            #pragma unroll
            for (int mf = 0; mf < 2; ++mf)
                #pragma unroll
                for (int nf = 0; nf < 4; ++nf)
                    #pragma unroll
                    for (int q = 0; q < 4; ++q) {
                        float e = fast_ex2(acc[mf][nf][q] * SCALE);
                        if (!offd) {
                            int rl = wm * 32 + mf * 16 + (q >> 1) * 8 + g;
                            int cl = wn * 32 + nf * 8 + tg * 2 + (q & 1);
                            if (rl == cl) e = 0.f;
                        }
                        racc[mf * 2 + (q >> 1)] += e;
                        cc8[nf * 2 + (q & 1)] += e;
                        acc[mf][nf][q] = 0.f;
                    }

            if (offd) {
                #pragma unroll
                for (int j = 0; j < 8; ++j) {
                    cc8[j] += __shfl_xor_sync(0xffffffffu, cc8[j], 4);
                    cc8[j] += __shfl_xor_sync(0xffffffffu, cc8[j], 8);
                    cc8[j] += __shfl_xor_sync(0xffffffffu, cc8[j], 16);
                }
                if (g == 0) {
                    float* dst = g_cs + (size_t)(band * 4 + wm) * TWO_N
                               + t * NT + wn * 32 + tg * 2;
                    #pragma unroll
                    for (int j = 0; j < 8; ++j) dst[(j >> 1) * 8 + (j & 1)] = cc8[j];
                }
            }

            cp_wait0();
            __syncthreads();
        }

        // ---- flush row partials for this band ----
        #pragma unroll
        for (int k2 = 0; k2 < 4; ++k2) {
            racc[k2] += __shfl_xor_sync(0xffffffffu, racc[k2], 1);
            racc[k2] += __shfl_xor_sync(0xffffffffu, racc[k2], 2);
        }
        if (tg == 0) {
            #pragma unroll
            for (int mf = 0; mf < 2; ++mf)
                #pragma unroll
                for (int h = 0; h < 2; ++h)
                    sred[wn * 128 + wm * 32 + mf * 16 + h * 8 + g] = racc[mf * 2 + h];
        }
        __syncthreads();
        if (tid < 128) {
            g_rsp[(half * 128 + band) * 128 + tid] =
                sred[tid] + sred[128 + tid] + sred[256 + tid] + sred[384 + tid];
        }
        __syncthreads();
    }
}

// ---------------- kernel 3b: combine row partials + transposed column sums ----------------
// grid 128 x 512: band B = blockIdx.x; 4 thread-chunks split the b' loop.
__global__ void rowfinal_kernel() {
    __shared__ float sm[512];
    const int B = blockIdx.x;
    const int rl = threadIdx.x & 127;
    const int chunk = threadIdx.x >> 7;
    const int r = B * 128 + rl;
    float sacc = 0.f;
    for (int b = chunk; b < B; b += 4) {
        const float* p4 = g_cs + (size_t)(b * 4) * TWO_N + r;
        sacc += p4[0] + p4[TWO_N] + p4[2 * TWO_N] + p4[3 * TWO_N];
    }
    sm[threadIdx.x] = sacc;
    __syncthreads();
    if (chunk == 0) {
        float tot = sm[rl] + sm[rl + 128] + sm[rl + 256] + sm[rl + 384]
                  + g_rsp[B * 128 + rl] + g_rsp[(128 + B) * 128 + rl];
        g_rowsum[r] = tot;
    }
}

// ---------------- kernel 4: two-stage final reduce ----------------
__global__ void reduce1_kernel() {
    __shared__ float sa[256], sb[256];
    int b = blockIdx.x, tid = threadIdx.x;
    float a = logf(g_rowsum[b * 256 + tid]);
    float pp = (tid < 128) ? g_pos[b * 128 + tid] : 0.f;
    sa[tid] = a; sb[tid] = pp;
    __syncthreads();
    for (int s = 128; s > 0; s >>= 1) {
        if (tid < s) { sa[tid] += sa[tid + s]; sb[tid] += sb[tid + s]; }
        __syncthreads();
    }
    if (tid == 0) { g_partA[b] = sa[0]; g_partB[b] = sb[0]; }
}

__global__ void reduce2_kernel(float* __restrict__ out) {
    __shared__ float sa[64], sb[64];
    int tid = threadIdx.x;
    sa[tid] = g_partA[tid]; sb[tid] = g_partB[tid];
    __syncthreads();
    for (int s = 32; s > 0; s >>= 1) {
        if (tid < s) { sa[tid] += sa[tid + s]; sb[tid] += sb[tid + s]; }
        __syncthreads();
    }
    if (tid == 0) out[0] = (sa[0] - 20.0f * sb[0]) / (float)TWO_N;
}

// ---------------- launch ----------------
extern "C" void kernel_launch(void* const* d_in, const int* in_sizes, int n_in,
                              void* d_out, int out_size) {
    const float* z1 = (const float*)d_in[0];
    const float* z2 = (const float*)d_in[1];
    float* out = (float*)d_out;

    normalize_kernel<<<2048, 256>>>(z1, z2);
    pos_kernel<<<1024, 256>>>(z1, z2);
    zero_rsp_kernel<<<32, 256>>>();
    cudaFuncSetAttribute(simloss_sym, cudaFuncAttributeMaxDynamicSharedMemorySize, SMEM_BYTES);
    simloss_sym<<<128, 512, SMEM_BYTES>>>();
    rowfinal_kernel<<<128, 512>>>();
    reduce1_kernel<<<64, 256>>>();
    reduce2_kernel<<<1, 64>>>(out);
}

// round 5
// speedup vs baseline: 1.8482x; 1.0689x over previous
#include <cuda_runtime.h>
#include <cuda_bf16.h>
#include <cstdint>

// ---------------- problem constants ----------------
#define TWO_N   16384
#define NHALF   8192
#define DK      256
#define MT      128
#define NT      128
#define SAPAD   264      // padded smem row stride in bf16 (528B; conflict-free ldmatrix)
#define TILE_BYTES2 (MT * SAPAD * 2)

// tile-list scheduling: 8256 upper-tri tiles over 148 CTAs
#define NCTA    148
#define BIGCHUNK 56
#define NBIG    116          // 116*56 + 32*55 = 8256
#define BIGLIN  (NBIG * BIGCHUNK)   // 6496
#define NSLOT   6

// smem: scratch (2KB) | A tile | B tile x2
#define SM_A       2048
#define SM_B       (SM_A + TILE_BYTES2)
#define SMEM_BYTES (SM_B + 2 * TILE_BYTES2)   // 204800 B

// ---------------- device scratch ----------------
__device__ __align__(16) __nv_bfloat16 g_zn[TWO_N * DK];
__device__ float g_rnorm[TWO_N];
__device__ float g_pos[NHALF];
__device__ float g_rowsum[TWO_N];
__device__ float g_partA[64];
__device__ float g_partB[64];
// column-sum contributions: [band(writer) * 4 + wm][col]  (32 MB, single-writer per tile)
__device__ float g_cs[128 * 4 * TWO_N];
// row partials: [band][slot][row]  (zeroed each run; single writer per slot)
__device__ float g_bandparts[128 * NSLOT * 128];

// ---------------- helpers ----------------
__device__ __forceinline__ float fast_ex2(float x) {
    float y;
    asm("ex2.approx.f32 %0, %1;" : "=f"(y) : "f"(x));
    return y;
}
__device__ __forceinline__ uint32_t smem_u32(const void* p) {
    uint32_t a;
    asm("{ .reg .u64 t; cvta.to.shared.u64 t, %1; cvt.u32.u64 %0, t; }" : "=r"(a) : "l"(p));
    return a;
}
__device__ __forceinline__ void cp16(uint32_t dst, const void* src) {
    asm volatile("cp.async.cg.shared.global [%0], [%1], 16;\n" :: "r"(dst), "l"(src));
}
__device__ __forceinline__ void cp_commit() { asm volatile("cp.async.commit_group;\n"); }
__device__ __forceinline__ void cp_wait0()  { asm volatile("cp.async.wait_group 0;\n"); }

__device__ __forceinline__ void ldsm4(uint32_t* r, uint32_t addr) {
    asm volatile("ldmatrix.sync.aligned.m8n8.x4.shared.b16 {%0,%1,%2,%3}, [%4];"
                 : "=r"(r[0]), "=r"(r[1]), "=r"(r[2]), "=r"(r[3]) : "r"(addr));
}
__device__ __forceinline__ void mma16816(float* c, const uint32_t* a, uint32_t b0, uint32_t b1) {
    asm volatile(
        "mma.sync.aligned.m16n8k16.row.col.f32.bf16.bf16.f32 "
        "{%0,%1,%2,%3}, {%4,%5,%6,%7}, {%8,%9}, {%0,%1,%2,%3};\n"
        : "+f"(c[0]), "+f"(c[1]), "+f"(c[2]), "+f"(c[3])
        : "r"(a[0]), "r"(a[1]), "r"(a[2]), "r"(a[3]), "r"(b0), "r"(b1));
}
__device__ __forceinline__ int chunk_owner(int L) {
    return (L < BIGLIN) ? (L / BIGCHUNK) : NBIG + (L - BIGLIN) / (BIGCHUNK - 1);
}

// ---------------- kernel 1: row-normalize -> bf16 ----------------
__global__ void normalize_kernel(const float* __restrict__ z1, const float* __restrict__ z2) {
    int warp = threadIdx.x >> 5, lane = threadIdx.x & 31;
    int row = blockIdx.x * 8 + warp;
    const float* src = (row < NHALF) ? (z1 + (size_t)row * DK)
                                     : (z2 + (size_t)(row - NHALF) * DK);
    float4 v0 = ((const float4*)src)[lane];
    float4 v1 = ((const float4*)src)[lane + 32];
    float ss = v0.x*v0.x + v0.y*v0.y + v0.z*v0.z + v0.w*v0.w
             + v1.x*v1.x + v1.y*v1.y + v1.z*v1.z + v1.w*v1.w;
    #pragma unroll
    for (int o = 16; o > 0; o >>= 1) ss += __shfl_xor_sync(0xffffffffu, ss, o);
    float rn = 1.0f / fmaxf(sqrtf(ss), 1e-6f);
    if (lane == 0) g_rnorm[row] = rn;

    __nv_bfloat162 w0a = __floats2bfloat162_rn(v0.x * rn, v0.y * rn);
    __nv_bfloat162 w0b = __floats2bfloat162_rn(v0.z * rn, v0.w * rn);
    __nv_bfloat162 w1a = __floats2bfloat162_rn(v1.x * rn, v1.y * rn);
    __nv_bfloat162 w1b = __floats2bfloat162_rn(v1.z * rn, v1.w * rn);
    uint2 p0, p1;
    memcpy(&p0.x, &w0a, 4); memcpy(&p0.y, &w0b, 4);
    memcpy(&p1.x, &w1a, 4); memcpy(&p1.y, &w1b, 4);
    uint2* dst = (uint2*)(g_zn + (size_t)row * DK);
    dst[lane]      = p0;
    dst[lane + 32] = p1;
}

// ---------------- kernel 2: fp32 positives ----------------
__global__ void pos_kernel(const float* __restrict__ z1, const float* __restrict__ z2) {
    int warp = threadIdx.x >> 5, lane = threadIdx.x & 31;
    int i = blockIdx.x * 8 + warp;
    const float* a = z1 + (size_t)i * DK;
    const float* b = z2 + (size_t)i * DK;
    float4 a0 = ((const float4*)a)[lane];
    float4 a1 = ((const float4*)a)[lane + 32];
    float4 b0 = ((const float4*)b)[lane];
    float4 b1 = ((const float4*)b)[lane + 32];
    float d = a0.x*b0.x + a0.y*b0.y + a0.z*b0.z + a0.w*b0.w
            + a1.x*b1.x + a1.y*b1.y + a1.z*b1.z + a1.w*b1.w;
    #pragma unroll
    for (int o = 16; o > 0; o >>= 1) d += __shfl_xor_sync(0xffffffffu, d, o);
    if (lane == 0) {
        float p = d * g_rnorm[i] * g_rnorm[i + NHALF];
        p = fminf(fmaxf(p, -1.0f + 1e-6f), 1.0f - 1e-6f);
        g_pos[i] = p;
    }
}

// ---------------- kernel 2b: zero g_bandparts ----------------
__global__ void zero_bp_kernel() {
    int i = blockIdx.x * 256 + threadIdx.x;    // 96 blocks: 96*256*4 = 98304 floats
    ((float4*)g_bandparts)[i] = make_float4(0.f, 0.f, 0.f, 0.f);
}

// ---------------- kernel 3: symmetric HMMA sim-GEMM, tile-list over 148 CTAs ----------------
// Snake band order: j even -> band j/2, j odd -> band 127-j/2 (sizes alternate big/small).
__global__ __launch_bounds__(512, 1) void simloss_sym2() {
    extern __shared__ char smem_raw[];
    const uint32_t sbase = smem_u32(smem_raw);
    const uint32_t sA  = sbase + SM_A;
    const uint32_t sB0 = sbase + SM_B;

    const int tid  = threadIdx.x;
    const int lane = tid & 31;
    const int w    = tid >> 5;
    const int wm   = w >> 2;
    const int wn   = w & 3;
    const int g    = lane >> 2;
    const int tg   = lane & 3;

    const int cta = blockIdx.x;
    const int s_lin = (cta < NBIG) ? cta * BIGCHUNK : BIGLIN + (cta - NBIG) * (BIGCHUNK - 1);
    const int e_lin = s_lin + ((cta < NBIG) ? BIGCHUNK : (BIGCHUNK - 1));

    // ldmatrix per-lane offsets
    const int lrow = lane & 15;
    const int lchk = lane >> 4;
    const uint32_t aOff  = (uint32_t)(((wm * 32 + lrow) * SAPAD + lchk * 8) * 2);
    const uint32_t aOff2 = aOff + (uint32_t)(16 * SAPAD * 2);
    const uint32_t bOff  = (uint32_t)(((wn * 32 + lrow) * SAPAD + lchk * 8) * 2);
    const uint32_t bOff2 = bOff + (uint32_t)(16 * SAPAD * 2);

    const float SCALE = 14.426950408889634f;   // 10 * log2(e)
    float* sred = (float*)smem_raw;            // 512 floats scratch

    int idx = s_lin;
    while (idx < e_lin) {
        // ---- map linear idx -> (band, tile t0) via snake order ----
        int cum = 0, band = 0;
        #pragma unroll 1
        for (int j = 0; j < 128; ++j) {
            int bb = (j & 1) ? (127 - (j >> 1)) : (j >> 1);
            int sz = 128 - bb;
            if (idx < cum + sz) { band = bb; break; }
            cum += sz;
        }
        const int t0 = band + (idx - cum);
        int t1 = t0 + (e_lin - idx) - 1;
        if (t1 > 127) t1 = 127;
        const int nb = t1 - t0 + 1;
        const int slot = cta - chunk_owner(cum);   // 0..NSLOT-1, single writer

        // ---- load A(band) + B(t0) ----
        {
            const __nv_bfloat16* gA = g_zn + (size_t)band * MT * DK;
            const __nv_bfloat16* gB = g_zn + (size_t)t0 * NT * DK;
            #pragma unroll
            for (int k = 0; k < 8; ++k) {
                int id = tid + k * 512;
                int r = id >> 5, ccx = id & 31;
                uint32_t so = (uint32_t)((r * SAPAD + ccx * 8) * 2);
                cp16(sA + so, gA + (size_t)r * DK + ccx * 8);
                cp16(sB0 + so, gB + (size_t)r * DK + ccx * 8);
            }
            cp_commit(); cp_wait0();
        }
        __syncthreads();

        float acc[2][4][4];
        #pragma unroll
        for (int mf = 0; mf < 2; ++mf)
            #pragma unroll
            for (int nf = 0; nf < 4; ++nf)
                #pragma unroll
                for (int q = 0; q < 4; ++q) acc[mf][nf][q] = 0.f;
        float racc[4] = {0.f, 0.f, 0.f, 0.f};

        for (int i2 = 0; i2 < nb; ++i2) {
            const int t = t0 + i2;
            const uint32_t sBc = sB0 + (uint32_t)((i2 & 1) * TILE_BYTES2);

            if (i2 + 1 < nb) {
                const uint32_t sBn = sB0 + (uint32_t)(((i2 + 1) & 1) * TILE_BYTES2);
                const __nv_bfloat16* gB = g_zn + (size_t)(t + 1) * NT * DK;
                #pragma unroll
                for (int k = 0; k < 8; ++k) {
                    int id = tid + k * 512;
                    int r = id >> 5, ccx = id & 31;
                    cp16(sBn + (uint32_t)((r * SAPAD + ccx * 8) * 2), gB + (size_t)r * DK + ccx * 8);
                }
            }
            cp_commit();

            #pragma unroll
            for (int ks = 0; ks < 16; ++ks) {
                const uint32_t kb = (uint32_t)(ks * 32);
                uint32_t a0[4], a1[4], bA[4], bB[4];
                ldsm4(a0, sA + aOff + kb);
                ldsm4(a1, sA + aOff2 + kb);
                ldsm4(bA, sBc + bOff + kb);
                ldsm4(bB, sBc + bOff2 + kb);

                mma16816(acc[0][0], a0, bA[0], bA[2]);
                mma16816(acc[1][0], a1, bA[0], bA[2]);
                mma16816(acc[0][1], a0, bA[1], bA[3]);
                mma16816(acc[1][1], a1, bA[1], bA[3]);
                mma16816(acc[0][2], a0, bB[0], bB[2]);
                mma16816(acc[1][2], a1, bB[0], bB[2]);
                mma16816(acc[0][3], a0, bB[1], bB[3]);
                mma16816(acc[1][3], a1, bB[1], bB[3]);
            }

            // ---- epilogue: exp, row accumulate, column accumulate (symmetry) ----
            const bool offd = (t != band);
            float cc8[8];
            #pragma unroll
            for (int j = 0; j < 8; ++j) cc8[j] = 0.f;

            #pragma unroll
            for (int mf = 0; mf < 2; ++mf)
                #pragma unroll
                for (int nf = 0; nf < 4; ++nf)
                    #pragma unroll
                    for (int q = 0; q < 4; ++q) {
                        float e = fast_ex2(acc[mf][nf][q] * SCALE);
                        if (!offd) {
                            int rl = wm * 32 + mf * 16 + (q >> 1) * 8 + g;
                            int cl = wn * 32 + nf * 8 + tg * 2 + (q & 1);
                            if (rl == cl) e = 0.f;
                        }
                        racc[mf * 2 + (q >> 1)] += e;
                        cc8[nf * 2 + (q & 1)] += e;
                        acc[mf][nf][q] = 0.f;
                    }

            if (offd) {
                #pragma unroll
                for (int j = 0; j < 8; ++j) {
                    cc8[j] += __shfl_xor_sync(0xffffffffu, cc8[j], 4);
                    cc8[j] += __shfl_xor_sync(0xffffffffu, cc8[j], 8);
                    cc8[j] += __shfl_xor_sync(0xffffffffu, cc8[j], 16);
                }
                if (g == 0) {
                    float* dst = g_cs + (size_t)(band * 4 + wm) * TWO_N
                               + t * NT + wn * 32 + tg * 2;
                    #pragma unroll
                    for (int j = 0; j < 8; ++j) dst[(j >> 1) * 8 + (j & 1)] = cc8[j];
                }
            }

            cp_wait0();
            __syncthreads();
        }

        // ---- flush row partials for this band segment ----
        #pragma unroll
        for (int k2 = 0; k2 < 4; ++k2) {
            racc[k2] += __shfl_xor_sync(0xffffffffu, racc[k2], 1);
            racc[k2] += __shfl_xor_sync(0xffffffffu, racc[k2], 2);
        }
        if (tg == 0) {
            #pragma unroll
            for (int mf = 0; mf < 2; ++mf)
                #pragma unroll
                for (int h = 0; h < 2; ++h)
                    sred[wn * 128 + wm * 32 + mf * 16 + h * 8 + g] = racc[mf * 2 + h];
        }
        __syncthreads();
        if (tid < 128) {
            g_bandparts[(band * NSLOT + slot) * 128 + tid] =
                sred[tid] + sred[128 + tid] + sred[256 + tid] + sred[384 + tid];
        }
        __syncthreads();

        idx += nb;
    }
}

// ---------------- kernel 3b: combine partials + transposed column sums, take log ----------------
__global__ void rowfinal_kernel() {
    __shared__ float sm[512];
    const int B = blockIdx.x;
    const int rl = threadIdx.x & 127;
    const int chunk = threadIdx.x >> 7;
    const int r = B * 128 + rl;
    float sacc = 0.f;
    for (int b = chunk; b < B; b += 4) {
        const float* p4 = g_cs + (size_t)(b * 4) * TWO_N + r;
        sacc += p4[0] + p4[TWO_N] + p4[2 * TWO_N] + p4[3 * TWO_N];
    }
    sm[threadIdx.x] = sacc;
    __syncthreads();
    if (chunk == 0) {
        float tot = sm[rl] + sm[rl + 128] + sm[rl + 256] + sm[rl + 384];
        const float* bp = g_bandparts + (size_t)B * NSLOT * 128 + rl;
        #pragma unroll
        for (int s = 0; s < NSLOT; ++s) tot += bp[s * 128];
        g_rowsum[r] = logf(tot);
    }
}

// ---------------- kernel 4: two-stage final reduce ----------------
__global__ void reduce1_kernel() {
    __shared__ float sa[256], sb[256];
    int b = blockIdx.x, tid = threadIdx.x;
    float a = g_rowsum[b * 256 + tid];          // already log
    float pp = (tid < 128) ? g_pos[b * 128 + tid] : 0.f;
    sa[tid] = a; sb[tid] = pp;
    __syncthreads();
    for (int s = 128; s > 0; s >>= 1) {
        if (tid < s) { sa[tid] += sa[tid + s]; sb[tid] += sb[tid + s]; }
        __syncthreads();
    }
    if (tid == 0) { g_partA[b] = sa[0]; g_partB[b] = sb[0]; }
}

__global__ void reduce2_kernel(float* __restrict__ out) {
    __shared__ float sa[64], sb[64];
    int tid = threadIdx.x;
    sa[tid] = g_partA[tid]; sb[tid] = g_partB[tid];
    __syncthreads();
    for (int s = 32; s > 0; s >>= 1) {
        if (tid < s) { sa[tid] += sa[tid + s]; sb[tid] += sb[tid + s]; }
        __syncthreads();
    }
    if (tid == 0) out[0] = (sa[0] - 20.0f * sb[0]) / (float)TWO_N;
}

// ---------------- launch ----------------
extern "C" void kernel_launch(void* const* d_in, const int* in_sizes, int n_in,
                              void* d_out, int out_size) {
    const float* z1 = (const float*)d_in[0];
    const float* z2 = (const float*)d_in[1];
    float* out = (float*)d_out;

    normalize_kernel<<<2048, 256>>>(z1, z2);
    pos_kernel<<<1024, 256>>>(z1, z2);
    zero_bp_kernel<<<96, 256>>>();
    cudaFuncSetAttribute(simloss_sym2, cudaFuncAttributeMaxDynamicSharedMemorySize, SMEM_BYTES);
    simloss_sym2<<<NCTA, 512, SMEM_BYTES>>>();
    rowfinal_kernel<<<128, 512>>>();
    reduce1_kernel<<<64, 256>>>();
    reduce2_kernel<<<1, 64>>>(out);
}